// round 10
// baseline (speedup 1.0000x reference)
#include <cuda_runtime.h>
#include <cstdint>

#define EPSV 0.1f

// tcgen05 compiles only on arch/family-specific targets (sm_103a/f), not plain sm_103.
#if defined(__CUDA_ARCH_FEAT_SM103_ALL) || defined(__CUDA_ARCH_FAMILY_SPECIFIC__) || defined(__CUDA_ARCH_FEAT_SM100_ALL)
#define TC_ENABLED 1
#else
#define TC_ENABLED 0
#endif

// ---------------- scratch globals (no allocations allowed) ----------------
__device__ __align__(1024) float g_xt [49152L * 224];   // x^T, (b*768+c, p) padded K=224
__device__ __align__(1024) float g_twp[384L * 224];     // tw padded K 196->224
__device__ __align__(1024) float g_w2p[256L * 384];     // w2 padded rows 196->256
__device__ __align__(1024) float g_H1 [49152L * 384];   // token YAT out
__device__ __align__(1024) float g_X2 [12544L * 768];   // after token mixing (b,p,c)
__device__ __align__(1024) float g_H3 [12544L * 3072];  // channel YAT out
__device__ float g_xn1[49152];
__device__ float g_xn2[12544];
__device__ float g_twn[384];
__device__ float g_cwn[3072];

// ---------------- helpers ----------------
__device__ __forceinline__ uint32_t smem_u32(const void* p) {
    uint32_t a;
    asm("{ .reg .u64 t; cvta.to.shared.u64 t, %1; cvt.u32.u64 %0, t; }" : "=r"(a) : "l"(p));
    return a;
}

// mask-based tf32 hi/lo split: h = top-10-mantissa truncation, l = masked remainder.
// All fixed-latency alu/fma ops (LOP3/FADD), rt=2 per SMSP.
__device__ __forceinline__ uint2 msplit(float v) {
    uint32_t u = __float_as_uint(v);
    uint32_t h = u & 0xFFFFE000u;
    float lf = v - __uint_as_float(h);
    uint32_t l = __float_as_uint(lf) & 0xFFFFE000u;
    return make_uint2(h, l);
}

#if TC_ENABLED
__device__ __forceinline__ void mbar_init(uint32_t a, uint32_t c) {
    asm volatile("mbarrier.init.shared.b64 [%0], %1;" :: "r"(a), "r"(c) : "memory");
}
__device__ __forceinline__ void mbar_arrive(uint32_t a) {
    asm volatile("mbarrier.arrive.shared.b64 _, [%0];" :: "r"(a) : "memory");
}
__device__ __forceinline__ void mbar_wait(uint32_t a, uint32_t ph) {
    asm volatile(
        "{\n\t.reg .pred P;\n"
        "W_%=:\n\t"
        "mbarrier.try_wait.parity.acquire.cta.shared::cta.b64 P, [%0], %1, 0x989680;\n\t"
        "@P bra.uni D_%=;\n\t"
        "bra.uni W_%=;\n"
        "D_%=:\n\t}"
        :: "r"(a), "r"(ph) : "memory");
}
__device__ __forceinline__ void tmem_alloc(uint32_t dst, uint32_t n) {
    asm volatile("tcgen05.alloc.cta_group::1.sync.aligned.shared::cta.b32 [%0], %1;"
                 :: "r"(dst), "r"(n) : "memory");
}
__device__ __forceinline__ void tmem_dealloc(uint32_t t, uint32_t n) {
    asm volatile("tcgen05.relinquish_alloc_permit.cta_group::1.sync.aligned;");
    asm volatile("tcgen05.dealloc.cta_group::1.sync.aligned.b32 %0, %1;" :: "r"(t), "r"(n));
}
__device__ __forceinline__ void mma_tf32(uint32_t d, uint64_t ad, uint64_t bd,
                                         uint32_t idesc, uint32_t en) {
    asm volatile(
        "{\n\t.reg .pred p;\n\tsetp.ne.u32 p, %4, 0;\n\t"
        "tcgen05.mma.cta_group::1.kind::tf32 [%0], %1, %2, %3, {%5,%5,%5,%5}, p;\n\t}"
        :: "r"(d), "l"(ad), "l"(bd), "r"(idesc), "r"(en), "r"(0u) : "memory");
}
__device__ __forceinline__ void mma_commit(uint32_t mbar) {
    asm volatile("tcgen05.commit.cta_group::1.mbarrier::arrive::one.shared::cluster.b64 [%0];"
                 :: "r"(mbar) : "memory");
}
#define TC_FENCE_AFTER()     asm volatile("tcgen05.fence::after_thread_sync;" ::: "memory")
#define TC_FENCE_BEFORE()    asm volatile("tcgen05.fence::before_thread_sync;" ::: "memory")
#define TMEM_WAIT_LD()       asm volatile("tcgen05.wait::ld.sync.aligned;" ::: "memory")
#define FENCE_ASYNC_SHARED() asm volatile("fence.proxy.async.shared::cta;" ::: "memory")

#define LDTM_X32(r, a) \
    asm volatile( \
        "tcgen05.ld.sync.aligned.32x32b.x32.b32 " \
        "{%0, %1, %2, %3, %4, %5, %6, %7, " \
        " %8, %9, %10, %11, %12, %13, %14, %15, " \
        " %16, %17, %18, %19, %20, %21, %22, %23, " \
        " %24, %25, %26, %27, %28, %29, %30, %31}, [%32];" \
        : "=r"((r)[0]),  "=r"((r)[1]),  "=r"((r)[2]),  "=r"((r)[3]), \
          "=r"((r)[4]),  "=r"((r)[5]),  "=r"((r)[6]),  "=r"((r)[7]), \
          "=r"((r)[8]),  "=r"((r)[9]),  "=r"((r)[10]), "=r"((r)[11]), \
          "=r"((r)[12]), "=r"((r)[13]), "=r"((r)[14]), "=r"((r)[15]), \
          "=r"((r)[16]), "=r"((r)[17]), "=r"((r)[18]), "=r"((r)[19]), \
          "=r"((r)[20]), "=r"((r)[21]), "=r"((r)[22]), "=r"((r)[23]), \
          "=r"((r)[24]), "=r"((r)[25]), "=r"((r)[26]), "=r"((r)[27]), \
          "=r"((r)[28]), "=r"((r)[29]), "=r"((r)[30]), "=r"((r)[31]) \
        : "r"(a))
#endif  // TC_ENABLED

// SW128 K-major SMEM descriptor base: LBO=1, SBO=64, layout=2, version=1
static constexpr unsigned long long DESC_BASE =
    (2ull << 61) | (1ull << 46) | (64ull << 32) | (1ull << 16);

// ---------------- prep kernels ----------------
// transpose + pad: g_xt[(b*768+c)*224 + p] = x[(b*196+p)*768 + c]
__global__ void xt_kernel(const float* __restrict__ x) {
    __shared__ float s[32][33];
    const int b = blockIdx.z, pt = blockIdx.y, ct = blockIdx.x;
    const int lane = threadIdx.x & 31, grp = threadIdx.x >> 5;
#pragma unroll
    for (int k = 0; k < 4; ++k) {
        int p = pt * 32 + grp + k * 8;
        float v = 0.f;
        if (p < 196) v = x[((long)(b * 196 + p)) * 768 + ct * 32 + lane];
        s[grp + k * 8][lane] = v;
    }
    __syncthreads();
#pragma unroll
    for (int k = 0; k < 4; ++k) {
        int c = grp + k * 8;
        g_xt[((long)(b * 768 + ct * 32 + c)) * 224 + pt * 32 + lane] = s[lane][c];
    }
}

// blocks [0,336): g_twp pad; [336,720): g_w2p pad; [720,768): g_twn (warp/row)
__global__ void pad_kernel(const float* __restrict__ tw, const float* __restrict__ w2) {
    int blk = blockIdx.x;
    if (blk < 336) {
        int i = blk * 256 + threadIdx.x;           // < 86016 = 384*224
        int r = i / 224, c = i - r * 224;
        g_twp[i] = (c < 196) ? tw[r * 196 + c] : 0.f;
    } else if (blk < 720) {
        int i = (blk - 336) * 256 + threadIdx.x;   // < 98304 = 256*384
        int r = i / 384, c = i - r * 384;
        g_w2p[i] = (r < 196) ? w2[r * 384 + c] : 0.f;
    } else {
        int row = (blk - 720) * 8 + (threadIdx.x >> 5);   // < 384
        int lane = threadIdx.x & 31;
        const float* p = tw + (long)row * 196;
        float s = 0.f;
        for (int k = lane; k < 196; k += 32) { float v = p[k]; s = fmaf(v, v, s); }
#pragma unroll
        for (int o = 16; o; o >>= 1) s += __shfl_xor_sync(0xffffffffu, s, o);
        if (lane == 0) g_twn[row] = s;
    }
}

// g_xn1 from g_xt rows (contiguous, pad zeros included)
__global__ void xnorm_kernel() {
    int row = blockIdx.x * 8 + (threadIdx.x >> 5);   // 6144 blocks -> 49152 rows
    int lane = threadIdx.x & 31;
    const float* p = g_xt + (long)row * 224;
    float s = 0.f;
    for (int k = lane; k < 224; k += 32) { float v = p[k]; s = fmaf(v, v, s); }
#pragma unroll
    for (int o = 16; o; o >>= 1) s += __shfl_xor_sync(0xffffffffu, s, o);
    if (lane == 0) g_xn1[row] = s;
}

// fused: rows [0,3072) -> g_cwn from cw; rows [3072,15616) -> g_xn2 from g_X2
__global__ void normcx_kernel(const float* __restrict__ cw) {
    int row = blockIdx.x * 8 + (threadIdx.x >> 5);   // 1952 blocks -> 15616 rows
    int lane = threadIdx.x & 31;
    const float* p = (row < 3072) ? (cw + (long)row * 768)
                                  : (g_X2 + (long)(row - 3072) * 768);
    float s = 0.f;
    for (int k = lane; k < 768; k += 32) { float v = p[k]; s = fmaf(v, v, s); }
#pragma unroll
    for (int o = 16; o; o >>= 1) s += __shfl_xor_sync(0xffffffffu, s, o);
    if (lane == 0) {
        if (row < 3072) g_cwn[row] = s; else g_xn2[row - 3072] = s;
    }
}

// ---------------------------------------------------------------------------
// Unified tcgen05 3xTF32 GEMM:  C[m,n] = sum_k A[m,k] * W[n,k]
// MODE 0: A=g_xt  K=224,  W=g_twp, NTILE=128, N=384;  epi = token YAT -> g_H1
// MODE 1: A=g_H1  K=384,  W=g_w2p, NTILE=256, N=196;  epi = residual+transpose -> g_X2
// MODE 2: A=g_X2  K=768,  W=cw,    NTILE=256, N=3072; epi = channel YAT -> g_H3
// MODE 3: A=g_H3  K=3072, W=w4,    NTILE=256, N=768;  epi = residual -> out
// Stage: [Ah 16K][Al 16K][Bh NTILE*128][Bl NTILE*128], 2 stages, K-chunk 32.
// ---------------------------------------------------------------------------
template<int MODE>
__global__ __launch_bounds__(256, 1) void gemm_tc(
    const float* __restrict__ Wext,
    const float* __restrict__ bias,
    const float* __restrict__ alpha,
    const float* __restrict__ resx,
    float* __restrict__ outx)
{
    constexpr int K     = (MODE == 0) ? 224 : (MODE == 1) ? 384 : (MODE == 2) ? 768 : 3072;
    constexpr int NTILE = (MODE == 0) ? 128 : 256;
    constexpr int NB    = NTILE / 32;       // B row-groups per chunk
    constexpr int NCH   = K / 32;           // K chunks
    constexpr int SG    = 32768 + NTILE * 256;  // stage bytes
    const float* A = (MODE == 0) ? g_xt : (MODE == 1) ? g_H1 : (MODE == 2) ? g_X2 : g_H3;
    const float* W = (MODE == 0) ? g_twp : (MODE == 1) ? g_w2p : Wext;
    float* out = (MODE == 0) ? g_H1 : (MODE == 1) ? g_X2 : (MODE == 2) ? g_H3 : outx;

    extern __shared__ char smem[];

#if TC_ENABLED
    constexpr uint32_t IDESC =
        (1u << 4) | (2u << 7) | (2u << 10) | ((NTILE / 8) << 17) | (8u << 24);

    const uint32_t sb = smem_u32(smem);
    const uint32_t FULL0 = sb + 16, EMPTY0 = sb + 32, DONE = sb + 48;
    const uint32_t stage0 = (sb + 5120 + 1023) & ~1023u;
    char* stage_ptr0 = smem + (stage0 - sb);
    float* lutW = (float*)(smem + 1024);
    float* lutB = (float*)(smem + 2048);

    const int tid = threadIdx.x;
    const int wid = tid >> 5, lane = tid & 31;
    const int m0 = blockIdx.y * 128;
    const int n0 = blockIdx.x * NTILE;

    if (tid == 0) {
        mbar_init(FULL0, 256);  mbar_init(FULL0 + 8, 256);
        mbar_init(EMPTY0, 1);   mbar_init(EMPTY0 + 8, 1);
        mbar_init(DONE, 1);
    }
    if (wid == 0) tmem_alloc(sb, NTILE);
    if (tid < NTILE) {
        if constexpr (MODE == 0) { lutW[tid] = g_twn[n0 + tid]; lutB[tid] = bias[n0 + tid]; }
        if constexpr (MODE == 2) { lutW[tid] = g_cwn[n0 + tid]; lutB[tid] = bias[n0 + tid]; }
        if constexpr (MODE == 1) { lutB[tid] = (tid < 196) ? bias[tid] : 0.f; }
        if constexpr (MODE == 3) { lutB[tid] = bias[n0 + tid]; }
    }
    __syncthreads();
    uint32_t tmem;
    asm volatile("ld.shared.b32 %0, [%1];" : "=r"(tmem) : "r"(sb));

    // producer mapping: 8 threads per 128B row; swizzle XOR is constant per thread
    const int r8 = tid >> 3;
    const int c8 = (tid & 7) * 4;
    const uint32_t obase = (uint32_t)(r8 * 128) + (uint32_t)(((tid & 7) * 16) ^ ((r8 & 7) << 4));
    const float* Abase = A + (long)(m0 + r8) * K + c8;
    const float* Bbase = W + (long)(n0 + r8) * K + c8;

    float4 pf[4 + NB];
#pragma unroll
    for (int q = 0; q < 4; ++q)  pf[q]     = *(const float4*)(Abase + q * (32 * K));
#pragma unroll
    for (int q = 0; q < NB; ++q) pf[4 + q] = *(const float4*)(Bbase + q * (32 * K));

    for (int t = 0; t < NCH; ++t) {
        const int s = t & 1;
        if (t >= 2) mbar_wait(EMPTY0 + s * 8, ((t >> 1) - 1) & 1);
        char* st = stage_ptr0 + s * SG;
#pragma unroll
        for (int q = 0; q < 4; ++q) {           // A hi/lo
            uint2 sx = msplit(pf[q].x), sy = msplit(pf[q].y),
                  sz = msplit(pf[q].z), sw = msplit(pf[q].w);
            *(uint4*)(st + q * 4096 + obase)         = make_uint4(sx.x, sy.x, sz.x, sw.x);
            *(uint4*)(st + 16384 + q * 4096 + obase) = make_uint4(sx.y, sy.y, sz.y, sw.y);
        }
#pragma unroll
        for (int q = 0; q < NB; ++q) {          // B hi/lo
            uint2 sx = msplit(pf[4 + q].x), sy = msplit(pf[4 + q].y),
                  sz = msplit(pf[4 + q].z), sw = msplit(pf[4 + q].w);
            *(uint4*)(st + 32768 + q * 4096 + obase)              = make_uint4(sx.x, sy.x, sz.x, sw.x);
            *(uint4*)(st + 32768 + NTILE * 128 + q * 4096 + obase) = make_uint4(sx.y, sy.y, sz.y, sw.y);
        }
        FENCE_ASYNC_SHARED();
        mbar_arrive(FULL0 + s * 8);

        // prefetch next chunk's operands while MMAs of this chunk run
        if (t + 1 < NCH) {
            const int kc = (t + 1) * 32;
#pragma unroll
            for (int q = 0; q < 4; ++q)  pf[q]     = *(const float4*)(Abase + q * (32 * K) + kc);
#pragma unroll
            for (int q = 0; q < NB; ++q) pf[4 + q] = *(const float4*)(Bbase + q * (32 * K) + kc);
        }

        if (tid == 0) {
            mbar_wait(FULL0 + s * 8, (t >> 1) & 1);
            const uint32_t sa = stage0 + s * SG;
            const uint64_t dah = DESC_BASE | ((uint64_t)(sa >> 4) & 0x3FFF);
            const uint64_t dal = DESC_BASE | ((uint64_t)((sa + 16384) >> 4) & 0x3FFF);
            const uint64_t dbh = DESC_BASE | ((uint64_t)((sa + 32768) >> 4) & 0x3FFF);
            const uint64_t dbl = DESC_BASE | ((uint64_t)((sa + 32768 + NTILE * 128) >> 4) & 0x3FFF);
#pragma unroll
            for (int ks = 0; ks < 4; ++ks) {
                const uint32_t en = (t > 0 || ks > 0) ? 1u : 0u;
                mma_tf32(tmem, dah + ks * 2, dbh + ks * 2, IDESC, en);
                mma_tf32(tmem, dah + ks * 2, dbl + ks * 2, IDESC, 1u);
                mma_tf32(tmem, dal + ks * 2, dbh + ks * 2, IDESC, 1u);
            }
            mma_commit(EMPTY0 + s * 8);
        }
    }
    if (tid == 0) mma_commit(DONE);
    mbar_wait(DONE, 0);
    TC_FENCE_AFTER();

    // ---- epilogue: half-warpgroups split columns; warps map TMEM subpartitions ----
    constexpr int NCS = NTILE / 64;                   // 32-col batches per warp
    const int cb0 = (wid >> 2) * (NTILE / 2);
    const long m = m0 + (wid & 3) * 32 + lane;

    float sc = 0.f, xv = 0.f;
    if constexpr (MODE == 0) { sc = powf(sqrtf(384.f / logf(385.f)), alpha[0]);  xv = g_xn1[m]; }
    if constexpr (MODE == 2) { sc = powf(sqrtf(3072.f / logf(3073.f)), alpha[0]); xv = g_xn2[m]; }

#pragma unroll
    for (int cs = 0; cs < NCS; ++cs) {
        uint32_t r[32];
        LDTM_X32(r, tmem + cb0 + cs * 32);
        TMEM_WAIT_LD();
        const int nb = cb0 + cs * 32;

        if constexpr (MODE == 0 || MODE == 2) {
            constexpr int LD = (MODE == 0) ? 384 : 3072;
            float* orow = out + m * LD + n0 + nb;
#pragma unroll
            for (int q = 0; q < 8; ++q) {
                float4 o;
                float* op = (float*)&o;
#pragma unroll
                for (int jj = 0; jj < 4; ++jj) {
                    const int j = q * 4 + jj;
                    const float d  = __uint_as_float(r[j]);
                    const float dt = d + lutB[nb + j];
                    const float ds = lutW[nb + j] + xv - 2.0f * d + EPSV;
                    op[jj] = sc * dt * dt / ds;
                }
                *(float4*)(orow + q * 4) = o;
            }
        } else if constexpr (MODE == 1) {
            // transpose write: m=(b,c), col=p; X2[(b,p,c)] = x + acc + b2[p]
            const long bq = m / 768;
            const int cq = (int)(m - bq * 768);
#pragma unroll
            for (int j = 0; j < 32; ++j) {
                const int p = nb + j;
                if (p < 196) {
                    const long o = (bq * 196 + p) * 768 + cq;
                    out[o] = resx[o] + __uint_as_float(r[j]) + lutB[p];
                }
            }
        } else {
            const float* rrow = g_X2 + m * 768 + n0 + nb;
            float* orow = out + m * 768 + n0 + nb;
#pragma unroll
            for (int q = 0; q < 8; ++q) {
                const float4 rv = *(const float4*)(rrow + q * 4);
                float4 o;
                o.x = rv.x + __uint_as_float(r[q * 4 + 0]) + lutB[nb + q * 4 + 0];
                o.y = rv.y + __uint_as_float(r[q * 4 + 1]) + lutB[nb + q * 4 + 1];
                o.z = rv.z + __uint_as_float(r[q * 4 + 2]) + lutB[nb + q * 4 + 2];
                o.w = rv.w + __uint_as_float(r[q * 4 + 3]) + lutB[nb + q * 4 + 3];
                *(float4*)(orow + q * 4) = o;
            }
        }
    }
    TC_FENCE_BEFORE();
    __syncthreads();
    if (wid == 0) tmem_dealloc(tmem, NTILE);

#else   // ------- naive fallback: compiles on plain sm_103, never selected on GB300 -------
    const int tid = threadIdx.x;
    const int m0 = blockIdx.y * 128, n0 = blockIdx.x * NTILE;
    for (int e = tid; e < 128 * NTILE; e += 256) {
        const int i = e / NTILE, j = e - i * NTILE;
        const long m = m0 + i;
        const int n = n0 + j;
        float d = 0.f;
        for (int k = 0; k < K; ++k) d = fmaf(A[m * K + k], W[(long)n * K + k], d);
        if constexpr (MODE == 0 || MODE == 2) {
            constexpr float NF = (MODE == 0) ? 384.f : 3072.f;
            const float scf = powf(sqrtf(NF / logf(NF + 1.f)), alpha[0]);
            const float xvf = (MODE == 0) ? g_xn1[m] : g_xn2[m];
            const float wnf = (MODE == 0) ? g_twn[n] : g_cwn[n];
            const float dt = d + bias[n];
            out[m * ((MODE == 0) ? 384 : 3072) + n] = scf * dt * dt / (wnf + xvf - 2.f * d + EPSV);
        } else if constexpr (MODE == 1) {
            if (n < 196) {
                const long bq = m / 768, cq = m % 768;
                const long o = (bq * 196 + n) * 768 + cq;
                out[o] = resx[o] + d + bias[n];
            }
        } else {
            const long o = m * 768 + n;
            out[o] = g_X2[o] + d + bias[n];
        }
    }
#endif  // TC_ENABLED
}

// ---------------------------------------------------------------------------
#define SM_T0 (6144 + 2 * (32768 + 128 * 256))   // 137216
#define SM_TB (6144 + 2 * (32768 + 256 * 256))   // 202752

extern "C" void kernel_launch(void* const* d_in, const int* in_sizes, int n_in,
                              void* d_out, int out_size) {
    (void)in_sizes; (void)n_in; (void)out_size;
    const float* x  = (const float*)d_in[0];
    const float* tw = (const float*)d_in[1];
    const float* tb = (const float*)d_in[2];
    const float* ta = (const float*)d_in[3];
    const float* w2 = (const float*)d_in[4];
    const float* b2 = (const float*)d_in[5];
    const float* cw = (const float*)d_in[6];
    const float* cb = (const float*)d_in[7];
    const float* ca = (const float*)d_in[8];
    const float* w4 = (const float*)d_in[9];
    const float* b4 = (const float*)d_in[10];
    float* outp = (float*)d_out;

    static int smem_set = 0;
    if (!smem_set) {
        cudaFuncSetAttribute(gemm_tc<0>, cudaFuncAttributeMaxDynamicSharedMemorySize, SM_T0);
        cudaFuncSetAttribute(gemm_tc<1>, cudaFuncAttributeMaxDynamicSharedMemorySize, SM_TB);
        cudaFuncSetAttribute(gemm_tc<2>, cudaFuncAttributeMaxDynamicSharedMemorySize, SM_TB);
        cudaFuncSetAttribute(gemm_tc<3>, cudaFuncAttributeMaxDynamicSharedMemorySize, SM_TB);
        smem_set = 1;
    }

    // prep: transpose/pads/norms
    xt_kernel<<<dim3(24, 7, 64), 256>>>(x);                 // g_xt
    pad_kernel<<<768, 256>>>(tw, w2);                       // g_twp, g_w2p, g_twn
    xnorm_kernel<<<6144, 256>>>();                          // g_xn1

    // token mixing (tcgen05)
    gemm_tc<0><<<dim3(3, 384), 256, SM_T0>>>(nullptr, tb, ta, nullptr, nullptr);   // -> g_H1
    gemm_tc<1><<<dim3(1, 384), 256, SM_TB>>>(nullptr, b2, nullptr, x, nullptr);    // -> g_X2

    // channel mixing (tcgen05)
    normcx_kernel<<<1952, 256>>>(cw);                                              // g_cwn, g_xn2
    gemm_tc<2><<<dim3(12, 98), 256, SM_TB>>>(cw, cb, ca, nullptr, nullptr);        // -> g_H3
    gemm_tc<3><<<dim3(3, 98), 256, SM_TB>>>(w4, b4, nullptr, nullptr, outp);       // -> out
}

// round 15
// speedup vs baseline: 1.0305x; 1.0305x over previous
#include <cuda_runtime.h>
#include <cstdint>

#define EPSV 0.1f

// tcgen05 compiles only on arch/family-specific targets (sm_103a/f), not plain sm_103.
#if defined(__CUDA_ARCH_FEAT_SM103_ALL) || defined(__CUDA_ARCH_FAMILY_SPECIFIC__) || defined(__CUDA_ARCH_FEAT_SM100_ALL)
#define TC_ENABLED 1
#else
#define TC_ENABLED 0
#endif

// ---------------- scratch globals (no allocations allowed) ----------------
__device__ __align__(1024) float g_xt [49152L * 224];   // x^T, (b*768+c, p) padded K=224
__device__ __align__(1024) float g_twp[384L * 224];     // tw padded K 196->224
__device__ __align__(1024) float g_w2p[256L * 384];     // w2 padded rows 196->256
__device__ __align__(1024) float g_H1 [49152L * 384];   // token YAT out
__device__ __align__(1024) float g_X2 [12544L * 768];   // after token mixing (b,p,c)
__device__ __align__(1024) float g_H3 [12544L * 3072];  // channel YAT out
__device__ float g_xn1[49152];
__device__ float g_xn2[12544];
__device__ float g_twn[384];
__device__ float g_cwn[3072];

// ---------------- helpers ----------------
__device__ __forceinline__ uint32_t smem_u32(const void* p) {
    uint32_t a;
    asm("{ .reg .u64 t; cvta.to.shared.u64 t, %1; cvt.u32.u64 %0, t; }" : "=r"(a) : "l"(p));
    return a;
}

// mask-based tf32 hi/lo split (LOP3 + FADD + LOP3, all fixed-lat)
__device__ __forceinline__ uint2 msplit(float v) {
    uint32_t u = __float_as_uint(v);
    uint32_t h = u & 0xFFFFE000u;
    float lf = v - __uint_as_float(h);
    uint32_t l = __float_as_uint(lf) & 0xFFFFE000u;
    return make_uint2(h, l);
}

#if TC_ENABLED
__device__ __forceinline__ void mbar_init(uint32_t a, uint32_t c) {
    asm volatile("mbarrier.init.shared.b64 [%0], %1;" :: "r"(a), "r"(c) : "memory");
}
__device__ __forceinline__ void mbar_arrive(uint32_t a) {
    asm volatile("mbarrier.arrive.shared.b64 _, [%0];" :: "r"(a) : "memory");
}
__device__ __forceinline__ void mbar_wait(uint32_t a, uint32_t ph) {
    asm volatile(
        "{\n\t.reg .pred P;\n"
        "W_%=:\n\t"
        "mbarrier.try_wait.parity.acquire.cta.shared::cta.b64 P, [%0], %1, 0x989680;\n\t"
        "@P bra.uni D_%=;\n\t"
        "bra.uni W_%=;\n"
        "D_%=:\n\t}"
        :: "r"(a), "r"(ph) : "memory");
}
__device__ __forceinline__ void tmem_alloc(uint32_t dst, uint32_t n) {
    asm volatile("tcgen05.alloc.cta_group::1.sync.aligned.shared::cta.b32 [%0], %1;"
                 :: "r"(dst), "r"(n) : "memory");
}
__device__ __forceinline__ void tmem_dealloc(uint32_t t, uint32_t n) {
    asm volatile("tcgen05.relinquish_alloc_permit.cta_group::1.sync.aligned;");
    asm volatile("tcgen05.dealloc.cta_group::1.sync.aligned.b32 %0, %1;" :: "r"(t), "r"(n));
}
__device__ __forceinline__ void mma_tf32(uint32_t d, uint64_t ad, uint64_t bd,
                                         uint32_t idesc, uint32_t en) {
    asm volatile(
        "{\n\t.reg .pred p;\n\tsetp.ne.u32 p, %4, 0;\n\t"
        "tcgen05.mma.cta_group::1.kind::tf32 [%0], %1, %2, %3, {%5,%5,%5,%5}, p;\n\t}"
        :: "r"(d), "l"(ad), "l"(bd), "r"(idesc), "r"(en), "r"(0u) : "memory");
}
__device__ __forceinline__ void mma_commit(uint32_t mbar) {
    asm volatile("tcgen05.commit.cta_group::1.mbarrier::arrive::one.shared::cluster.b64 [%0];"
                 :: "r"(mbar) : "memory");
}
#define TC_FENCE_AFTER()     asm volatile("tcgen05.fence::after_thread_sync;" ::: "memory")
#define TC_FENCE_BEFORE()    asm volatile("tcgen05.fence::before_thread_sync;" ::: "memory")
#define TMEM_WAIT_LD()       asm volatile("tcgen05.wait::ld.sync.aligned;" ::: "memory")
#define FENCE_ASYNC_SHARED() asm volatile("fence.proxy.async.shared::cta;" ::: "memory")

#define LDTM_X32(r, a) \
    asm volatile( \
        "tcgen05.ld.sync.aligned.32x32b.x32.b32 " \
        "{%0, %1, %2, %3, %4, %5, %6, %7, " \
        " %8, %9, %10, %11, %12, %13, %14, %15, " \
        " %16, %17, %18, %19, %20, %21, %22, %23, " \
        " %24, %25, %26, %27, %28, %29, %30, %31}, [%32];" \
        : "=r"((r)[0]),  "=r"((r)[1]),  "=r"((r)[2]),  "=r"((r)[3]), \
          "=r"((r)[4]),  "=r"((r)[5]),  "=r"((r)[6]),  "=r"((r)[7]), \
          "=r"((r)[8]),  "=r"((r)[9]),  "=r"((r)[10]), "=r"((r)[11]), \
          "=r"((r)[12]), "=r"((r)[13]), "=r"((r)[14]), "=r"((r)[15]), \
          "=r"((r)[16]), "=r"((r)[17]), "=r"((r)[18]), "=r"((r)[19]), \
          "=r"((r)[20]), "=r"((r)[21]), "=r"((r)[22]), "=r"((r)[23]), \
          "=r"((r)[24]), "=r"((r)[25]), "=r"((r)[26]), "=r"((r)[27]), \
          "=r"((r)[28]), "=r"((r)[29]), "=r"((r)[30]), "=r"((r)[31]) \
        : "r"(a))
#endif  // TC_ENABLED

// SW128 K-major SMEM descriptor base: LBO=1, SBO=64, layout=2, version=1
static constexpr unsigned long long DESC_BASE =
    (2ull << 61) | (1ull << 46) | (64ull << 32) | (1ull << 16);

// ---------------- prep kernels ----------------
__global__ void xt_kernel(const float* __restrict__ x) {
    __shared__ float s[32][33];
    const int b = blockIdx.z, pt = blockIdx.y, ct = blockIdx.x;
    const int lane = threadIdx.x & 31, grp = threadIdx.x >> 5;
#pragma unroll
    for (int k = 0; k < 4; ++k) {
        int p = pt * 32 + grp + k * 8;
        float v = 0.f;
        if (p < 196) v = x[((long)(b * 196 + p)) * 768 + ct * 32 + lane];
        s[grp + k * 8][lane] = v;
    }
    __syncthreads();
#pragma unroll
    for (int k = 0; k < 4; ++k) {
        int c = grp + k * 8;
        g_xt[((long)(b * 768 + ct * 32 + c)) * 224 + pt * 32 + lane] = s[lane][c];
    }
}

__global__ void pad_kernel(const float* __restrict__ tw, const float* __restrict__ w2) {
    int blk = blockIdx.x;
    if (blk < 336) {
        int i = blk * 256 + threadIdx.x;           // 384*224
        int r = i / 224, c = i - r * 224;
        g_twp[i] = (c < 196) ? tw[r * 196 + c] : 0.f;
    } else if (blk < 720) {
        int i = (blk - 336) * 256 + threadIdx.x;   // 256*384
        int r = i / 384, c = i - r * 384;
        g_w2p[i] = (r < 196) ? w2[r * 384 + c] : 0.f;
    } else {
        int row = (blk - 720) * 8 + (threadIdx.x >> 5);
        int lane = threadIdx.x & 31;
        const float* p = tw + (long)row * 196;
        float s = 0.f;
        for (int k = lane; k < 196; k += 32) { float v = p[k]; s = fmaf(v, v, s); }
#pragma unroll
        for (int o = 16; o; o >>= 1) s += __shfl_xor_sync(0xffffffffu, s, o);
        if (lane == 0) g_twn[row] = s;
    }
}

__global__ void xnorm_kernel() {
    int row = blockIdx.x * 8 + (threadIdx.x >> 5);
    int lane = threadIdx.x & 31;
    const float* p = g_xt + (long)row * 224;
    float s = 0.f;
    for (int k = lane; k < 224; k += 32) { float v = p[k]; s = fmaf(v, v, s); }
#pragma unroll
    for (int o = 16; o; o >>= 1) s += __shfl_xor_sync(0xffffffffu, s, o);
    if (lane == 0) g_xn1[row] = s;
}

__global__ void normcx_kernel(const float* __restrict__ cw) {
    int row = blockIdx.x * 8 + (threadIdx.x >> 5);   // 15616 rows
    int lane = threadIdx.x & 31;
    const float* p = (row < 3072) ? (cw + (long)row * 768)
                                  : (g_X2 + (long)(row - 3072) * 768);
    float s = 0.f;
    for (int k = lane; k < 768; k += 32) { float v = p[k]; s = fmaf(v, v, s); }
#pragma unroll
    for (int o = 16; o; o >>= 1) s += __shfl_xor_sync(0xffffffffu, s, o);
    if (lane == 0) {
        if (row < 3072) g_cwn[row] = s; else g_xn2[row - 3072] = s;
    }
}

// ---------------------------------------------------------------------------
// Persistent tcgen05 3xTF32 GEMM:  C[m,n] = sum_k A[m,k] * W[n,k]
// Grid = 148 CTAs; each owns a contiguous tile range; TMEM alloc once;
// double-buffered TMEM accumulators overlap epilogue(j-1) with MMA(j).
// MODE 0: A=g_xt  K=224,  W=g_twp, NTILE=128, MT=384, NT=3;  token YAT -> g_H1
// MODE 1: A=g_H1  K=384,  W=g_w2p, NTILE=256, MT=384, NT=1;  residual+transpose -> g_X2
// MODE 2: A=g_X2  K=768,  W=cw,    NTILE=256, MT=98,  NT=12; channel YAT -> g_H3
// MODE 3: A=g_H3  K=3072, W=w4,    NTILE=256, MT=98,  NT=3;  residual -> out
// ---------------------------------------------------------------------------
template<int MODE>
__global__ __launch_bounds__(256, 1) void gemm_tc(
    const float* __restrict__ Wext,
    const float* __restrict__ bias,
    const float* __restrict__ alpha,
    const float* __restrict__ resx,
    float* __restrict__ outx)
{
    constexpr int K     = (MODE == 0) ? 224 : (MODE == 1) ? 384 : (MODE == 2) ? 768 : 3072;
    constexpr int NTILE = (MODE == 0) ? 128 : 256;
    constexpr int NB    = NTILE / 32;
    constexpr int NCH   = K / 32;
    constexpr int SG    = 32768 + NTILE * 256;
    constexpr int MT    = (MODE <= 1) ? 384 : 98;
    constexpr int NT    = (MODE == 0) ? 3 : (MODE == 1) ? 1 : (MODE == 2) ? 12 : 3;
    constexpr int TILES = MT * NT;
    constexpr int TMEMC = (MODE == 0) ? 256 : 512;
    const float* A = (MODE == 0) ? g_xt : (MODE == 1) ? g_H1 : (MODE == 2) ? g_X2 : g_H3;
    const float* W = (MODE == 0) ? g_twp : (MODE == 1) ? g_w2p : Wext;
    const float* wn = (MODE == 0) ? g_twn : g_cwn;
    float* out = (MODE == 0) ? g_H1 : (MODE == 1) ? g_X2 : (MODE == 2) ? g_H3 : outx;

    extern __shared__ char smem[];

#if TC_ENABLED
    constexpr uint32_t IDESC =
        (1u << 4) | (2u << 7) | (2u << 10) | ((NTILE / 8) << 17) | (8u << 24);

    const uint32_t sb = smem_u32(smem);
    const uint32_t FULL0 = sb + 16, EMPTY0 = sb + 32, MDONE0 = sb + 48;
    const uint32_t stage0 = (sb + 128 + 1023) & ~1023u;
    char* stage_ptr0 = smem + (stage0 - sb);

    const int tid = threadIdx.x;
    const int wid = tid >> 5, lane = tid & 31;

    if (tid == 0) {
        mbar_init(FULL0, 256);  mbar_init(FULL0 + 8, 256);
        mbar_init(EMPTY0, 1);   mbar_init(EMPTY0 + 8, 1);
        mbar_init(MDONE0, 1);   mbar_init(MDONE0 + 8, 1);
    }
    if (wid == 0) tmem_alloc(sb, TMEMC);
    __syncthreads();
    uint32_t tmem;
    asm volatile("ld.shared.b32 %0, [%1];" : "=r"(tmem) : "r"(sb));

    // tile range for this CTA
    const int cta = blockIdx.x, G = gridDim.x;
    const int q = TILES / G, rr = TILES % G;
    const int lo  = cta * q + (cta < rr ? cta : rr);
    const int cnt = q + (cta < rr ? 1 : 0);

    // producer mapping: 8 threads per 128B row; swizzle XOR constant per thread
    const int r8 = tid >> 3;
    const int c8 = (tid & 7) * 4;
    const uint32_t obase = (uint32_t)(r8 * 128) + (uint32_t)(((tid & 7) * 16) ^ ((r8 & 7) << 4));

    const float sc = (MODE == 0) ? powf(sqrtf(384.f / logf(385.f)), alpha[0])
                   : (MODE == 2) ? powf(sqrtf(3072.f / logf(3073.f)), alpha[0]) : 0.f;

    // ---- epilogue (reads TMEM buffer jj&1 for tile lo+jj) ----
    auto epilogue = [&](int jj) {
        mbar_wait(MDONE0 + (jj & 1) * 8, (jj >> 1) & 1);
        TC_FENCE_AFTER();
        const int idx = lo + jj;
        const int ni = idx / MT, mi = idx - ni * MT;
        const int m0 = mi * 128, n0 = ni * NTILE;
        const uint32_t dbuf = tmem + (jj & 1) * NTILE;
        constexpr int NCS = NTILE / 64;
        const int cb0 = (wid >> 2) * (NTILE / 2);
        const long m = m0 + (wid & 3) * 32 + lane;
        const float xv = (MODE == 0) ? g_xn1[m] : (MODE == 2) ? g_xn2[m] : 0.f;

#pragma unroll
        for (int cs = 0; cs < NCS; ++cs) {
            uint32_t r[32];
            LDTM_X32(r, dbuf + cb0 + cs * 32);
            TMEM_WAIT_LD();
            const int nb = cb0 + cs * 32;

            if constexpr (MODE == 0 || MODE == 2) {
                constexpr int LD = (MODE == 0) ? 384 : 3072;
                float* orow = out + m * LD + n0 + nb;
#pragma unroll
                for (int qq = 0; qq < 8; ++qq) {
                    const float4 bv = *(const float4*)(bias + n0 + nb + qq * 4);
                    const float4 wv = *(const float4*)(wn + n0 + nb + qq * 4);
                    const float* bp = (const float*)&bv;
                    const float* wp = (const float*)&wv;
                    float4 o;
                    float* op = (float*)&o;
#pragma unroll
                    for (int jj2 = 0; jj2 < 4; ++jj2) {
                        const float d  = __uint_as_float(r[qq * 4 + jj2]);
                        const float dt = d + bp[jj2];
                        const float ds = wp[jj2] + xv - 2.0f * d + EPSV;
                        op[jj2] = sc * dt * dt / ds;
                    }
                    *(float4*)(orow + qq * 4) = o;
                }
            } else if constexpr (MODE == 1) {
                const long bq = m / 768;
                const int cq = (int)(m - bq * 768);
#pragma unroll
                for (int j = 0; j < 32; ++j) {
                    const int p = nb + j;
                    if (p < 196) {
                        const long o = (bq * 196 + p) * 768 + cq;
                        out[o] = resx[o] + __uint_as_float(r[j]) + __ldg(bias + p);
                    }
                }
            } else {
                const float* rrow = g_X2 + m * 768 + n0 + nb;
                float* orow = out + m * 768 + n0 + nb;
#pragma unroll
                for (int qq = 0; qq < 8; ++qq) {
                    const float4 bv = *(const float4*)(bias + n0 + nb + qq * 4);
                    const float4 rv = *(const float4*)(rrow + qq * 4);
                    float4 o;
                    o.x = rv.x + __uint_as_float(r[qq * 4 + 0]) + bv.x;
                    o.y = rv.y + __uint_as_float(r[qq * 4 + 1]) + bv.y;
                    o.z = rv.z + __uint_as_float(r[qq * 4 + 2]) + bv.z;
                    o.w = rv.w + __uint_as_float(r[qq * 4 + 3]) + bv.w;
                    *(float4*)(orow + qq * 4) = o;
                }
            }
        }
        TC_FENCE_BEFORE();
    };

    int g = 0;   // global chunk counter (stages shared across tiles)
    for (int j = 0; j < cnt; ++j) {
        const int idx = lo + j;
        const int ni = idx / MT, mi = idx - ni * MT;
        const int m0 = mi * 128, n0 = ni * NTILE;
        const float* Abase = A + (long)(m0 + r8) * K + c8;
        const float* Bbase = W + (long)(n0 + r8) * K + c8;
        const uint32_t dbuf = tmem + (j & 1) * NTILE;

        float4 pf[4 + NB];
#pragma unroll
        for (int qq = 0; qq < 4; ++qq)  pf[qq]     = *(const float4*)(Abase + qq * (32 * K));
#pragma unroll
        for (int qq = 0; qq < NB; ++qq) pf[4 + qq] = *(const float4*)(Bbase + qq * (32 * K));

        for (int t = 0; t < NCH; ++t, ++g) {
            const int s = g & 1;
            if (g >= 2) mbar_wait(EMPTY0 + s * 8, ((g >> 1) - 1) & 1);
            char* st = stage_ptr0 + s * SG;
#pragma unroll
            for (int qq = 0; qq < 4; ++qq) {           // A hi/lo
                uint2 sx = msplit(pf[qq].x), sy = msplit(pf[qq].y),
                      sz = msplit(pf[qq].z), sw = msplit(pf[qq].w);
                *(uint4*)(st + qq * 4096 + obase)         = make_uint4(sx.x, sy.x, sz.x, sw.x);
                *(uint4*)(st + 16384 + qq * 4096 + obase) = make_uint4(sx.y, sy.y, sz.y, sw.y);
            }
#pragma unroll
            for (int qq = 0; qq < NB; ++qq) {          // B hi/lo
                uint2 sx = msplit(pf[4 + qq].x), sy = msplit(pf[4 + qq].y),
                      sz = msplit(pf[4 + qq].z), sw = msplit(pf[4 + qq].w);
                *(uint4*)(st + 32768 + qq * 4096 + obase)               = make_uint4(sx.x, sy.x, sz.x, sw.x);
                *(uint4*)(st + 32768 + NTILE * 128 + qq * 4096 + obase) = make_uint4(sx.y, sy.y, sz.y, sw.y);
            }
            FENCE_ASYNC_SHARED();
            mbar_arrive(FULL0 + s * 8);

            if (t + 1 < NCH) {
                const int kc = (t + 1) * 32;
#pragma unroll
                for (int qq = 0; qq < 4; ++qq)  pf[qq]     = *(const float4*)(Abase + qq * (32 * K) + kc);
#pragma unroll
                for (int qq = 0; qq < NB; ++qq) pf[4 + qq] = *(const float4*)(Bbase + qq * (32 * K) + kc);
            }

            if (tid == 0) {
                mbar_wait(FULL0 + s * 8, (g >> 1) & 1);
                const uint32_t sa = stage0 + s * SG;
                const uint64_t dah = DESC_BASE | ((uint64_t)(sa >> 4) & 0x3FFF);
                const uint64_t dal = DESC_BASE | ((uint64_t)((sa + 16384) >> 4) & 0x3FFF);
                const uint64_t dbh = DESC_BASE | ((uint64_t)((sa + 32768) >> 4) & 0x3FFF);
                const uint64_t dbl = DESC_BASE | ((uint64_t)((sa + 32768 + NTILE * 128) >> 4) & 0x3FFF);
#pragma unroll
                for (int ks = 0; ks < 4; ++ks) {
                    const uint32_t en = (t > 0 || ks > 0) ? 1u : 0u;
                    mma_tf32(dbuf, dah + ks * 2, dbh + ks * 2, IDESC, en);
                    mma_tf32(dbuf, dah + ks * 2, dbl + ks * 2, IDESC, 1u);
                    mma_tf32(dbuf, dal + ks * 2, dbh + ks * 2, IDESC, 1u);
                }
                mma_commit(EMPTY0 + s * 8);
                if (t == NCH - 1) mma_commit(MDONE0 + (j & 1) * 8);
            }
        }
        if (j > 0) epilogue(j - 1);      // overlaps with tile j's MMAs
    }
    epilogue(cnt - 1);
    __syncthreads();
    if (wid == 0) tmem_dealloc(tmem, TMEMC);

#else   // ------- naive fallback: compiles on plain sm_103, never selected on GB300 -------
    const int cta = blockIdx.x, G = gridDim.x;
    const int q = TILES / G, rr = TILES % G;
    const int lo  = cta * q + (cta < rr ? cta : rr);
    const int cnt = q + (cta < rr ? 1 : 0);
    const int tid = threadIdx.x;
    for (int j = 0; j < cnt; ++j) {
        const int idx = lo + j;
        const int ni = idx / MT, mi = idx - ni * MT;
        const int m0 = mi * 128, n0 = ni * NTILE;
        for (int e = tid; e < 128 * NTILE; e += 256) {
            const int i = e / NTILE, jn = e - i * NTILE;
            const long m = m0 + i;
            const int n = n0 + jn;
            float d = 0.f;
            for (int k = 0; k < K; ++k) d = fmaf(A[m * K + k], W[(long)n * K + k], d);
            if constexpr (MODE == 0 || MODE == 2) {
                constexpr float NF = (MODE == 0) ? 384.f : 3072.f;
                const float scf = powf(sqrtf(NF / logf(NF + 1.f)), alpha[0]);
                const float xvf = (MODE == 0) ? g_xn1[m] : g_xn2[m];
                const float dt = d + bias[n];
                out[m * ((MODE == 0) ? 384 : 3072) + n] =
                    scf * dt * dt / (wn[n] + xvf - 2.f * d + EPSV);
            } else if constexpr (MODE == 1) {
                if (n < 196) {
                    const long bq = m / 768, cq = m % 768;
                    const long o = (bq * 196 + n) * 768 + cq;
                    out[o] = resx[o] + d + bias[n];
                }
            } else {
                const long o = m * 768 + n;
                out[o] = g_X2[o] + d + bias[n];
            }
        }
    }
#endif  // TC_ENABLED
}

// ---------------------------------------------------------------------------
#define SM_T0 (2048 + 2 * (32768 + 128 * 256))   // ~133KB
#define SM_TB (2048 + 2 * (32768 + 256 * 256))   // ~198KB

extern "C" void kernel_launch(void* const* d_in, const int* in_sizes, int n_in,
                              void* d_out, int out_size) {
    (void)in_sizes; (void)n_in; (void)out_size;
    const float* x  = (const float*)d_in[0];
    const float* tw = (const float*)d_in[1];
    const float* tb = (const float*)d_in[2];
    const float* ta = (const float*)d_in[3];
    const float* w2 = (const float*)d_in[4];
    const float* b2 = (const float*)d_in[5];
    const float* cw = (const float*)d_in[6];
    const float* cb = (const float*)d_in[7];
    const float* ca = (const float*)d_in[8];
    const float* w4 = (const float*)d_in[9];
    const float* b4 = (const float*)d_in[10];
    float* outp = (float*)d_out;

    static int smem_set = 0;
    if (!smem_set) {
        cudaFuncSetAttribute(gemm_tc<0>, cudaFuncAttributeMaxDynamicSharedMemorySize, SM_T0);
        cudaFuncSetAttribute(gemm_tc<1>, cudaFuncAttributeMaxDynamicSharedMemorySize, SM_TB);
        cudaFuncSetAttribute(gemm_tc<2>, cudaFuncAttributeMaxDynamicSharedMemorySize, SM_TB);
        cudaFuncSetAttribute(gemm_tc<3>, cudaFuncAttributeMaxDynamicSharedMemorySize, SM_TB);
        smem_set = 1;
    }

    // prep
    xt_kernel<<<dim3(24, 7, 64), 256>>>(x);                 // g_xt
    pad_kernel<<<768, 256>>>(tw, w2);                       // g_twp, g_w2p, g_twn
    xnorm_kernel<<<6144, 256>>>();                          // g_xn1

    // token mixing (persistent tcgen05)
    gemm_tc<0><<<148, 256, SM_T0>>>(nullptr, tb, ta, nullptr, nullptr);   // -> g_H1
    gemm_tc<1><<<148, 256, SM_TB>>>(nullptr, b2, nullptr, x, nullptr);    // -> g_X2

    // channel mixing (persistent tcgen05)
    normcx_kernel<<<1952, 256>>>(cw);                                     // g_cwn, g_xn2
    gemm_tc<2><<<148, 256, SM_TB>>>(cw, cb, ca, nullptr, nullptr);        // -> g_H3
    gemm_tc<3><<<148, 256, SM_TB>>>(w4, b4, nullptr, nullptr, outp);      // -> out
}

// round 16
// speedup vs baseline: 1.1390x; 1.1053x over previous
#include <cuda_runtime.h>
#include <cstdint>

#define EPSV 0.1f

// tcgen05 compiles only on arch/family-specific targets (sm_103a/f), not plain sm_103.
#if defined(__CUDA_ARCH_FEAT_SM103_ALL) || defined(__CUDA_ARCH_FAMILY_SPECIFIC__) || defined(__CUDA_ARCH_FEAT_SM100_ALL)
#define TC_ENABLED 1
#else
#define TC_ENABLED 0
#endif

#define THREADS 512

// ---------------- scratch globals (no allocations allowed) ----------------
__device__ __align__(1024) float g_xt [49152L * 224];   // x^T, (b*768+c, p) padded K=224
__device__ __align__(1024) float g_twp[384L * 224];     // tw padded K 196->224
__device__ __align__(1024) float g_w2p[256L * 384];     // w2 padded rows 196->256
__device__ __align__(1024) float g_H1 [49152L * 384];   // token YAT out
__device__ __align__(1024) float g_X2 [12544L * 768];   // after token mixing (b,p,c)
__device__ __align__(1024) float g_H3 [12544L * 3072];  // channel YAT out
__device__ float g_xn1[49152];
__device__ float g_xn2[12544];
__device__ float g_twn[384];
__device__ float g_cwn[3072];

// ---------------- helpers ----------------
__device__ __forceinline__ uint32_t smem_u32(const void* p) {
    uint32_t a;
    asm("{ .reg .u64 t; cvta.to.shared.u64 t, %1; cvt.u32.u64 %0, t; }" : "=r"(a) : "l"(p));
    return a;
}

// mask-based tf32 hi/lo split (LOP3 + FADD + LOP3, all fixed-lat)
__device__ __forceinline__ uint2 msplit(float v) {
    uint32_t u = __float_as_uint(v);
    uint32_t h = u & 0xFFFFE000u;
    float lf = v - __uint_as_float(h);
    uint32_t l = __float_as_uint(lf) & 0xFFFFE000u;
    return make_uint2(h, l);
}

#if TC_ENABLED
__device__ __forceinline__ void mbar_init(uint32_t a, uint32_t c) {
    asm volatile("mbarrier.init.shared.b64 [%0], %1;" :: "r"(a), "r"(c) : "memory");
}
__device__ __forceinline__ void mbar_arrive(uint32_t a) {
    asm volatile("mbarrier.arrive.shared.b64 _, [%0];" :: "r"(a) : "memory");
}
__device__ __forceinline__ void mbar_wait(uint32_t a, uint32_t ph) {
    asm volatile(
        "{\n\t.reg .pred P;\n"
        "W_%=:\n\t"
        "mbarrier.try_wait.parity.acquire.cta.shared::cta.b64 P, [%0], %1, 0x989680;\n\t"
        "@P bra.uni D_%=;\n\t"
        "bra.uni W_%=;\n"
        "D_%=:\n\t}"
        :: "r"(a), "r"(ph) : "memory");
}
__device__ __forceinline__ void tmem_alloc(uint32_t dst, uint32_t n) {
    asm volatile("tcgen05.alloc.cta_group::1.sync.aligned.shared::cta.b32 [%0], %1;"
                 :: "r"(dst), "r"(n) : "memory");
}
__device__ __forceinline__ void tmem_dealloc(uint32_t t, uint32_t n) {
    asm volatile("tcgen05.relinquish_alloc_permit.cta_group::1.sync.aligned;");
    asm volatile("tcgen05.dealloc.cta_group::1.sync.aligned.b32 %0, %1;" :: "r"(t), "r"(n));
}
__device__ __forceinline__ void mma_tf32(uint32_t d, uint64_t ad, uint64_t bd,
                                         uint32_t idesc, uint32_t en) {
    asm volatile(
        "{\n\t.reg .pred p;\n\tsetp.ne.u32 p, %4, 0;\n\t"
        "tcgen05.mma.cta_group::1.kind::tf32 [%0], %1, %2, %3, {%5,%5,%5,%5}, p;\n\t}"
        :: "r"(d), "l"(ad), "l"(bd), "r"(idesc), "r"(en), "r"(0u) : "memory");
}
__device__ __forceinline__ void mma_commit(uint32_t mbar) {
    asm volatile("tcgen05.commit.cta_group::1.mbarrier::arrive::one.shared::cluster.b64 [%0];"
                 :: "r"(mbar) : "memory");
}
#define TC_FENCE_AFTER()     asm volatile("tcgen05.fence::after_thread_sync;" ::: "memory")
#define TC_FENCE_BEFORE()    asm volatile("tcgen05.fence::before_thread_sync;" ::: "memory")
#define TMEM_WAIT_LD()       asm volatile("tcgen05.wait::ld.sync.aligned;" ::: "memory")
#define FENCE_ASYNC_SHARED() asm volatile("fence.proxy.async.shared::cta;" ::: "memory")

#define LDTM_X32(r, a) \
    asm volatile( \
        "tcgen05.ld.sync.aligned.32x32b.x32.b32 " \
        "{%0, %1, %2, %3, %4, %5, %6, %7, " \
        " %8, %9, %10, %11, %12, %13, %14, %15, " \
        " %16, %17, %18, %19, %20, %21, %22, %23, " \
        " %24, %25, %26, %27, %28, %29, %30, %31}, [%32];" \
        : "=r"((r)[0]),  "=r"((r)[1]),  "=r"((r)[2]),  "=r"((r)[3]), \
          "=r"((r)[4]),  "=r"((r)[5]),  "=r"((r)[6]),  "=r"((r)[7]), \
          "=r"((r)[8]),  "=r"((r)[9]),  "=r"((r)[10]), "=r"((r)[11]), \
          "=r"((r)[12]), "=r"((r)[13]), "=r"((r)[14]), "=r"((r)[15]), \
          "=r"((r)[16]), "=r"((r)[17]), "=r"((r)[18]), "=r"((r)[19]), \
          "=r"((r)[20]), "=r"((r)[21]), "=r"((r)[22]), "=r"((r)[23]), \
          "=r"((r)[24]), "=r"((r)[25]), "=r"((r)[26]), "=r"((r)[27]), \
          "=r"((r)[28]), "=r"((r)[29]), "=r"((r)[30]), "=r"((r)[31]) \
        : "r"(a))
#endif  // TC_ENABLED

// SW128 K-major SMEM descriptor base: LBO=1, SBO=64, layout=2, version=1
static constexpr unsigned long long DESC_BASE =
    (2ull << 61) | (1ull << 46) | (64ull << 32) | (1ull << 16);

// ---------------- prep kernels ----------------
__global__ void xt_kernel(const float* __restrict__ x) {
    __shared__ float s[32][33];
    const int b = blockIdx.z, pt = blockIdx.y, ct = blockIdx.x;
    const int lane = threadIdx.x & 31, grp = threadIdx.x >> 5;
#pragma unroll
    for (int k = 0; k < 4; ++k) {
        int p = pt * 32 + grp + k * 8;
        float v = 0.f;
        if (p < 196) v = x[((long)(b * 196 + p)) * 768 + ct * 32 + lane];
        s[grp + k * 8][lane] = v;
    }
    __syncthreads();
#pragma unroll
    for (int k = 0; k < 4; ++k) {
        int c = grp + k * 8;
        g_xt[((long)(b * 768 + ct * 32 + c)) * 224 + pt * 32 + lane] = s[lane][c];
    }
}

__global__ void pad_kernel(const float* __restrict__ tw, const float* __restrict__ w2) {
    int blk = blockIdx.x;
    if (blk < 336) {
        int i = blk * 256 + threadIdx.x;           // 384*224
        int r = i / 224, c = i - r * 224;
        g_twp[i] = (c < 196) ? tw[r * 196 + c] : 0.f;
    } else if (blk < 720) {
        int i = (blk - 336) * 256 + threadIdx.x;   // 256*384
        int r = i / 384, c = i - r * 384;
        g_w2p[i] = (r < 196) ? w2[r * 384 + c] : 0.f;
    } else {
        int row = (blk - 720) * 8 + (threadIdx.x >> 5);
        int lane = threadIdx.x & 31;
        const float* p = tw + (long)row * 196;
        float s = 0.f;
        for (int k = lane; k < 196; k += 32) { float v = p[k]; s = fmaf(v, v, s); }
#pragma unroll
        for (int o = 16; o; o >>= 1) s += __shfl_xor_sync(0xffffffffu, s, o);
        if (lane == 0) g_twn[row] = s;
    }
}

__global__ void xnorm_kernel() {
    int row = blockIdx.x * 8 + (threadIdx.x >> 5);
    int lane = threadIdx.x & 31;
    const float* p = g_xt + (long)row * 224;
    float s = 0.f;
    for (int k = lane; k < 224; k += 32) { float v = p[k]; s = fmaf(v, v, s); }
#pragma unroll
    for (int o = 16; o; o >>= 1) s += __shfl_xor_sync(0xffffffffu, s, o);
    if (lane == 0) g_xn1[row] = s;
}

__global__ void normcx_kernel(const float* __restrict__ cw) {
    int row = blockIdx.x * 8 + (threadIdx.x >> 5);   // 15616 rows
    int lane = threadIdx.x & 31;
    const float* p = (row < 3072) ? (cw + (long)row * 768)
                                  : (g_X2 + (long)(row - 3072) * 768);
    float s = 0.f;
    for (int k = lane; k < 768; k += 32) { float v = p[k]; s = fmaf(v, v, s); }
#pragma unroll
    for (int o = 16; o; o >>= 1) s += __shfl_xor_sync(0xffffffffu, s, o);
    if (lane == 0) {
        if (row < 3072) g_cwn[row] = s; else g_xn2[row - 3072] = s;
    }
}

// ---------------------------------------------------------------------------
// Persistent tcgen05 3xTF32 GEMM, 512 threads:  C[m,n] = sum_k A[m,k]*W[n,k]
// MODE 0: A=g_xt  K=224,  W=g_twp, NTILE=128, MT=384, NT=3;  token YAT -> g_H1
// MODE 1: A=g_H1  K=384,  W=g_w2p, NTILE=256, MT=384, NT=1;  residual+transpose -> g_X2
// MODE 2: A=g_X2  K=768,  W=cw,    NTILE=256, MT=98,  NT=12; channel YAT -> g_H3
// MODE 3: A=g_H3  K=3072, W=w4,    NTILE=256, MT=98,  NT=3;  residual -> out
// ---------------------------------------------------------------------------
template<int MODE>
__global__ __launch_bounds__(THREADS, 1) void gemm_tc(
    const float* __restrict__ Wext,
    const float* __restrict__ bias,
    const float* __restrict__ alpha,
    const float* __restrict__ resx,
    float* __restrict__ outx)
{
    constexpr int K     = (MODE == 0) ? 224 : (MODE == 1) ? 384 : (MODE == 2) ? 768 : 3072;
    constexpr int NTILE = (MODE == 0) ? 128 : 256;
    constexpr int NB2   = NTILE / 64;        // B 64-row passes
    constexpr int NCH   = K / 32;
    constexpr int SG    = 32768 + NTILE * 256;
    constexpr int MT    = (MODE <= 1) ? 384 : 98;
    constexpr int NT    = (MODE == 0) ? 3 : (MODE == 1) ? 1 : (MODE == 2) ? 12 : 3;
    constexpr int TILES = MT * NT;
    constexpr int TMEMC = (MODE == 0) ? 256 : 512;
    const float* A = (MODE == 0) ? g_xt : (MODE == 1) ? g_H1 : (MODE == 2) ? g_X2 : g_H3;
    const float* W = (MODE == 0) ? g_twp : (MODE == 1) ? g_w2p : Wext;
    const float* wn = (MODE == 0) ? g_twn : g_cwn;
    float* out = (MODE == 0) ? g_H1 : (MODE == 1) ? g_X2 : (MODE == 2) ? g_H3 : outx;

    extern __shared__ char smem[];

#if TC_ENABLED
    constexpr uint32_t IDESC =
        (1u << 4) | (2u << 7) | (2u << 10) | ((NTILE / 8) << 17) | (8u << 24);

    const uint32_t sb = smem_u32(smem);
    const uint32_t FULL0 = sb + 16, EMPTY0 = sb + 32, MDONE0 = sb + 48;
    const uint32_t stage0 = (sb + 128 + 1023) & ~1023u;
    char* stage_ptr0 = smem + (stage0 - sb);

    const int tid = threadIdx.x;
    const int wid = tid >> 5, lane = tid & 31;

    if (tid == 0) {
        mbar_init(FULL0, THREADS);  mbar_init(FULL0 + 8, THREADS);
        mbar_init(EMPTY0, 1);       mbar_init(EMPTY0 + 8, 1);
        mbar_init(MDONE0, 1);       mbar_init(MDONE0 + 8, 1);
    }
    if (wid == 0) tmem_alloc(sb, TMEMC);
    __syncthreads();
    uint32_t tmem;
    asm volatile("ld.shared.b32 %0, [%1];" : "=r"(tmem) : "r"(sb));

    // tile range for this CTA
    const int cta = blockIdx.x, G = gridDim.x;
    const int q = TILES / G, rr = TILES % G;
    const int lo  = cta * q + (cta < rr ? cta : rr);
    const int cnt = q + (cta < rr ? 1 : 0);

    // producer mapping: 8 threads per 128B row; 512 threads cover 64 rows/pass
    const int r8 = tid >> 3;                 // 0..63
    const int c8 = (tid & 7) * 4;
    const uint32_t obase = (uint32_t)(r8 * 128) + (uint32_t)(((tid & 7) * 16) ^ ((r8 & 7) << 4));

    const float sc = (MODE == 0) ? powf(sqrtf(384.f / logf(385.f)), alpha[0])
                   : (MODE == 2) ? powf(sqrtf(3072.f / logf(3073.f)), alpha[0]) : 0.f;

    // ---- epilogue: 16 warps = 4 col-groups x 4 subpartition warps ----
    auto epilogue = [&](int jj) {
        mbar_wait(MDONE0 + (jj & 1) * 8, (jj >> 1) & 1);
        TC_FENCE_AFTER();
        const int idx = lo + jj;
        const int ni = idx / MT, mi = idx - ni * MT;
        const int m0 = mi * 128, n0 = ni * NTILE;
        const uint32_t dbuf = tmem + (jj & 1) * NTILE;
        constexpr int NCS = NTILE / 128;         // 32-col batches per warp
        const int cb0 = (wid >> 2) * (NTILE / 4);
        const long m = m0 + (wid & 3) * 32 + lane;
        const float xv = (MODE == 0) ? g_xn1[m] : (MODE == 2) ? g_xn2[m] : 0.f;

#pragma unroll
        for (int cs = 0; cs < NCS; ++cs) {
            uint32_t r[32];
            LDTM_X32(r, dbuf + cb0 + cs * 32);
            TMEM_WAIT_LD();
            const int nb = cb0 + cs * 32;

            if constexpr (MODE == 0 || MODE == 2) {
                constexpr int LD = (MODE == 0) ? 384 : 3072;
                float* orow = out + m * LD + n0 + nb;
#pragma unroll
                for (int qq = 0; qq < 8; ++qq) {
                    const float4 bv = *(const float4*)(bias + n0 + nb + qq * 4);
                    const float4 wv = *(const float4*)(wn + n0 + nb + qq * 4);
                    const float* bp = (const float*)&bv;
                    const float* wp = (const float*)&wv;
                    float4 o;
                    float* op = (float*)&o;
#pragma unroll
                    for (int jj2 = 0; jj2 < 4; ++jj2) {
                        const float d  = __uint_as_float(r[qq * 4 + jj2]);
                        const float dt = d + bp[jj2];
                        const float ds = wp[jj2] + xv - 2.0f * d + EPSV;
                        op[jj2] = sc * dt * dt / ds;
                    }
                    *(float4*)(orow + qq * 4) = o;
                }
            } else if constexpr (MODE == 1) {
                const long bq = m / 768;
                const int cq = (int)(m - bq * 768);
#pragma unroll
                for (int j = 0; j < 32; ++j) {
                    const int p = nb + j;
                    if (p < 196) {
                        const long o = (bq * 196 + p) * 768 + cq;
                        out[o] = resx[o] + __uint_as_float(r[j]) + __ldg(bias + p);
                    }
                }
            } else {
                const float* rrow = g_X2 + m * 768 + n0 + nb;
                float* orow = out + m * 768 + n0 + nb;
#pragma unroll
                for (int qq = 0; qq < 8; ++qq) {
                    const float4 bv = *(const float4*)(bias + n0 + nb + qq * 4);
                    const float4 rv = *(const float4*)(rrow + qq * 4);
                    float4 o;
                    o.x = rv.x + __uint_as_float(r[qq * 4 + 0]) + bv.x;
                    o.y = rv.y + __uint_as_float(r[qq * 4 + 1]) + bv.y;
                    o.z = rv.z + __uint_as_float(r[qq * 4 + 2]) + bv.z;
                    o.w = rv.w + __uint_as_float(r[qq * 4 + 3]) + bv.w;
                    *(float4*)(orow + qq * 4) = o;
                }
            }
        }
        TC_FENCE_BEFORE();
    };

    int g = 0;   // global chunk counter (stages shared across tiles)
    for (int j = 0; j < cnt; ++j) {
        const int idx = lo + j;
        const int ni = idx / MT, mi = idx - ni * MT;
        const int m0 = mi * 128, n0 = ni * NTILE;
        const float* Abase = A + (long)(m0 + r8) * K + c8;
        const float* Bbase = W + (long)(n0 + r8) * K + c8;
        const uint32_t dbuf = tmem + (j & 1) * NTILE;

        float4 pf[2 + NB2];
#pragma unroll
        for (int qq = 0; qq < 2; ++qq)   pf[qq]     = *(const float4*)(Abase + qq * (64 * K));
#pragma unroll
        for (int qq = 0; qq < NB2; ++qq) pf[2 + qq] = *(const float4*)(Bbase + qq * (64 * K));

        for (int t = 0; t < NCH; ++t, ++g) {
            const int s = g & 1;
            if (g >= 2) mbar_wait(EMPTY0 + s * 8, ((g >> 1) - 1) & 1);
            char* st = stage_ptr0 + s * SG;
#pragma unroll
            for (int qq = 0; qq < 2; ++qq) {           // A hi/lo, 64 rows/pass
                uint2 sx = msplit(pf[qq].x), sy = msplit(pf[qq].y),
                      sz = msplit(pf[qq].z), sw = msplit(pf[qq].w);
                *(uint4*)(st + qq * 8192 + obase)         = make_uint4(sx.x, sy.x, sz.x, sw.x);
                *(uint4*)(st + 16384 + qq * 8192 + obase) = make_uint4(sx.y, sy.y, sz.y, sw.y);
            }
#pragma unroll
            for (int qq = 0; qq < NB2; ++qq) {         // B hi/lo
                uint2 sx = msplit(pf[2 + qq].x), sy = msplit(pf[2 + qq].y),
                      sz = msplit(pf[2 + qq].z), sw = msplit(pf[2 + qq].w);
                *(uint4*)(st + 32768 + qq * 8192 + obase)               = make_uint4(sx.x, sy.x, sz.x, sw.x);
                *(uint4*)(st + 32768 + NTILE * 128 + qq * 8192 + obase) = make_uint4(sx.y, sy.y, sz.y, sw.y);
            }
            FENCE_ASYNC_SHARED();
            mbar_arrive(FULL0 + s * 8);

            if (t + 1 < NCH) {
                const int kc = (t + 1) * 32;
#pragma unroll
                for (int qq = 0; qq < 2; ++qq)   pf[qq]     = *(const float4*)(Abase + qq * (64 * K) + kc);
#pragma unroll
                for (int qq = 0; qq < NB2; ++qq) pf[2 + qq] = *(const float4*)(Bbase + qq * (64 * K) + kc);
            }

            if (tid == 0) {
                mbar_wait(FULL0 + s * 8, (g >> 1) & 1);
                const uint32_t sa = stage0 + s * SG;
                const uint64_t dah = DESC_BASE | ((uint64_t)(sa >> 4) & 0x3FFF);
                const uint64_t dal = DESC_BASE | ((uint64_t)((sa + 16384) >> 4) & 0x3FFF);
                const uint64_t dbh = DESC_BASE | ((uint64_t)((sa + 32768) >> 4) & 0x3FFF);
                const uint64_t dbl = DESC_BASE | ((uint64_t)((sa + 32768 + NTILE * 128) >> 4) & 0x3FFF);
#pragma unroll
                for (int ks = 0; ks < 4; ++ks) {
                    const uint32_t en = (t > 0 || ks > 0) ? 1u : 0u;
                    mma_tf32(dbuf, dah + ks * 2, dbh + ks * 2, IDESC, en);
                    mma_tf32(dbuf, dah + ks * 2, dbl + ks * 2, IDESC, 1u);
                    mma_tf32(dbuf, dal + ks * 2, dbh + ks * 2, IDESC, 1u);
                }
                mma_commit(EMPTY0 + s * 8);
                if (t == NCH - 1) mma_commit(MDONE0 + (j & 1) * 8);
            }
        }
        if (j > 0) epilogue(j - 1);      // overlaps with tile j's MMAs
    }
    epilogue(cnt - 1);
    __syncthreads();
    if (wid == 0) tmem_dealloc(tmem, TMEMC);

#else   // ------- naive fallback: compiles on plain sm_103, never selected on GB300 -------
    const int cta = blockIdx.x, G = gridDim.x;
    const int q = TILES / G, rr = TILES % G;
    const int lo  = cta * q + (cta < rr ? cta : rr);
    const int cnt = q + (cta < rr ? 1 : 0);
    const int tid = threadIdx.x;
    for (int j = 0; j < cnt; ++j) {
        const int idx = lo + j;
        const int ni = idx / MT, mi = idx - ni * MT;
        const int m0 = mi * 128, n0 = ni * NTILE;
        for (int e = tid; e < 128 * NTILE; e += THREADS) {
            const int i = e / NTILE, jn = e - i * NTILE;
            const long m = m0 + i;
            const int n = n0 + jn;
            float d = 0.f;
            for (int k = 0; k < K; ++k) d = fmaf(A[m * K + k], W[(long)n * K + k], d);
            if constexpr (MODE == 0 || MODE == 2) {
                constexpr float NF = (MODE == 0) ? 384.f : 3072.f;
                const float scf = powf(sqrtf(NF / logf(NF + 1.f)), alpha[0]);
                const float xvf = (MODE == 0) ? g_xn1[m] : g_xn2[m];
                const float dt = d + bias[n];
                out[m * ((MODE == 0) ? 384 : 3072) + n] =
                    scf * dt * dt / (wn[n] + xvf - 2.f * d + EPSV);
            } else if constexpr (MODE == 1) {
                if (n < 196) {
                    const long bq = m / 768, cq = m % 768;
                    const long o = (bq * 196 + n) * 768 + cq;
                    out[o] = resx[o] + d + bias[n];
                }
            } else {
                const long o = m * 768 + n;
                out[o] = g_X2[o] + d + bias[n];
            }
        }
    }
#endif  // TC_ENABLED
}

// ---------------------------------------------------------------------------
#define SM_T0 (2048 + 2 * (32768 + 128 * 256))   // ~133KB
#define SM_TB (2048 + 2 * (32768 + 256 * 256))   // ~198KB

extern "C" void kernel_launch(void* const* d_in, const int* in_sizes, int n_in,
                              void* d_out, int out_size) {
    (void)in_sizes; (void)n_in; (void)out_size;
    const float* x  = (const float*)d_in[0];
    const float* tw = (const float*)d_in[1];
    const float* tb = (const float*)d_in[2];
    const float* ta = (const float*)d_in[3];
    const float* w2 = (const float*)d_in[4];
    const float* b2 = (const float*)d_in[5];
    const float* cw = (const float*)d_in[6];
    const float* cb = (const float*)d_in[7];
    const float* ca = (const float*)d_in[8];
    const float* w4 = (const float*)d_in[9];
    const float* b4 = (const float*)d_in[10];
    float* outp = (float*)d_out;

    static int smem_set = 0;
    if (!smem_set) {
        cudaFuncSetAttribute(gemm_tc<0>, cudaFuncAttributeMaxDynamicSharedMemorySize, SM_T0);
        cudaFuncSetAttribute(gemm_tc<1>, cudaFuncAttributeMaxDynamicSharedMemorySize, SM_TB);
        cudaFuncSetAttribute(gemm_tc<2>, cudaFuncAttributeMaxDynamicSharedMemorySize, SM_TB);
        cudaFuncSetAttribute(gemm_tc<3>, cudaFuncAttributeMaxDynamicSharedMemorySize, SM_TB);
        smem_set = 1;
    }

    // prep
    xt_kernel<<<dim3(24, 7, 64), 256>>>(x);                 // g_xt
    pad_kernel<<<768, 256>>>(tw, w2);                       // g_twp, g_w2p, g_twn
    xnorm_kernel<<<6144, 256>>>();                          // g_xn1

    // token mixing (persistent tcgen05)
    gemm_tc<0><<<148, THREADS, SM_T0>>>(nullptr, tb, ta, nullptr, nullptr);   // -> g_H1
    gemm_tc<1><<<148, THREADS, SM_TB>>>(nullptr, b2, nullptr, x, nullptr);    // -> g_X2

    // channel mixing (persistent tcgen05)
    normcx_kernel<<<1952, 256>>>(cw);                                         // g_cwn, g_xn2
    gemm_tc<2><<<148, THREADS, SM_TB>>>(cw, cb, ca, nullptr, nullptr);        // -> g_H3
    gemm_tc<3><<<148, THREADS, SM_TB>>>(w4, b4, nullptr, nullptr, outp);      // -> out
}